// round 14
// baseline (speedup 1.0000x reference)
#include <cuda_runtime.h>
#include <cuda_bf16.h>
#include <math.h>
#include <stdint.h>

// ---------------- static scratch ----------------
static __device__ __nv_bfloat16 g_wqb[4096u * 4096u];   // W' = q - z (exact ints in bf16)
static __device__ __nv_bfloat16 g_xhi[10240u * 4096u];  // bf16 hi part of x
static __device__ __nv_bfloat16 g_xlo[10240u * 4096u];  // bf16 lo residual of x
static __device__ float g_out[10240u * 4096u];          // pre-quant GEMM output
__device__ unsigned g_wmm[2];
__device__ unsigned g_cmin[32], g_cmax[32];
__device__ float g_s3[32], g_z3[32];
__device__ float g_sw;

// ---- monotone float <-> uint encoding ----
__device__ __forceinline__ unsigned f2o(float f) {
    unsigned u = __float_as_uint(f);
    return (u & 0x80000000u) ? ~u : (u | 0x80000000u);
}
__device__ __forceinline__ float o2f(unsigned u) {
    unsigned v = (u & 0x80000000u) ? (u ^ 0x80000000u) : ~u;
    return __uint_as_float(v);
}
__device__ __forceinline__ float fq(float v, float s, float z) {
    float q = rintf(__fadd_rn(__fdiv_rn(v, s), z));
    q = fminf(fmaxf(q, 0.0f), 255.0f);
    return __fmul_rn(__fsub_rn(q, z), s);
}

// ---------------- PTX helpers ----------------
__device__ __forceinline__ uint32_t smem_u32(const void* p) {
    uint32_t a;
    asm("{ .reg .u64 t; cvta.to.shared.u64 t, %1; cvt.u32.u64 %0, t; }" : "=r"(a) : "l"(p));
    return a;
}
__device__ __forceinline__ void cpa16(uint32_t d, const void* s) {
    asm volatile("cp.async.cg.shared.global [%0], [%1], 16;" :: "r"(d), "l"(s));
}
__device__ __forceinline__ void cpa_commit() { asm volatile("cp.async.commit_group;" ::: "memory"); }
template<int N> __device__ __forceinline__ void cpa_wait() {
    asm volatile("cp.async.wait_group %0;" :: "n"(N) : "memory");
}
__device__ __forceinline__ void ldsm_x4(uint32_t& r0, uint32_t& r1, uint32_t& r2, uint32_t& r3,
                                        uint32_t addr) {
    asm volatile("ldmatrix.sync.aligned.m8n8.x4.shared.b16 {%0,%1,%2,%3}, [%4];"
                 : "=r"(r0), "=r"(r1), "=r"(r2), "=r"(r3) : "r"(addr));
}
__device__ __forceinline__ void mma16816(float* c, const uint32_t* a, const uint32_t* b) {
    asm volatile("mma.sync.aligned.m16n8k16.row.col.f32.bf16.bf16.f32 "
                 "{%0,%1,%2,%3}, {%4,%5,%6,%7}, {%8,%9}, {%0,%1,%2,%3};"
                 : "+f"(c[0]), "+f"(c[1]), "+f"(c[2]), "+f"(c[3])
                 : "r"(a[0]), "r"(a[1]), "r"(a[2]), "r"(a[3]), "r"(b[0]), "r"(b[1]));
}

// ---------------- kernel 0: reset reduction state ----------------
__global__ void init_kernel() {
    if (threadIdx.x == 0) { g_wmm[0] = 0xFFFFFFFFu; g_wmm[1] = 0u; }
    if (threadIdx.x < 32) { g_cmin[threadIdx.x] = 0xFFFFFFFFu; g_cmax[threadIdx.x] = 0u; }
}

// ---------------- kernel 1: weight min/max ----------------
__global__ void wminmax_kernel(const float4* __restrict__ w4, int n4) {
    float mn = INFINITY, mx = -INFINITY;
    for (int i = blockIdx.x * blockDim.x + threadIdx.x; i < n4; i += gridDim.x * blockDim.x) {
        float4 v = w4[i];
        mn = fminf(mn, fminf(fminf(v.x, v.y), fminf(v.z, v.w)));
        mx = fmaxf(mx, fmaxf(fmaxf(v.x, v.y), fmaxf(v.z, v.w)));
    }
    #pragma unroll
    for (int o = 16; o; o >>= 1) {
        mn = fminf(mn, __shfl_xor_sync(0xffffffffu, mn, o));
        mx = fmaxf(mx, __shfl_xor_sync(0xffffffffu, mx, o));
    }
    __shared__ float smn[8], smx[8];
    if ((threadIdx.x & 31) == 0) { smn[threadIdx.x >> 5] = mn; smx[threadIdx.x >> 5] = mx; }
    __syncthreads();
    if (threadIdx.x == 0) {
        for (int i = 1; i < (int)(blockDim.x >> 5); i++) { mn = fminf(mn, smn[i]); mx = fmaxf(mx, smx[i]); }
        atomicMin(&g_wmm[0], f2o(mn));
        atomicMax(&g_wmm[1], f2o(mx));
    }
}

// ---------------- kernel 2: W' = q - z into bf16 (exact) ----------------
__global__ void quantw_kernel(const float4* __restrict__ w4, int n4) {
    float mn = o2f(g_wmm[0]), mx = o2f(g_wmm[1]);
    float s = __fdiv_rn(__fsub_rn(mx, mn), 255.0f);
    float z = -rintf(__fdiv_rn(mn, s));
    if (blockIdx.x == 0 && threadIdx.x == 0) g_sw = s;
    __nv_bfloat162* dst = reinterpret_cast<__nv_bfloat162*>(g_wqb);
    for (int i = blockIdx.x * blockDim.x + threadIdx.x; i < n4; i += gridDim.x * blockDim.x) {
        float4 v = w4[i];
        float q0 = fminf(fmaxf(rintf(__fadd_rn(__fdiv_rn(v.x, s), z)), 0.f), 255.f) - z;
        float q1 = fminf(fmaxf(rintf(__fadd_rn(__fdiv_rn(v.y, s), z)), 0.f), 255.f) - z;
        float q2 = fminf(fmaxf(rintf(__fadd_rn(__fdiv_rn(v.z, s), z)), 0.f), 255.f) - z;
        float q3 = fminf(fmaxf(rintf(__fadd_rn(__fdiv_rn(v.w, s), z)), 0.f), 255.f) - z;
        __nv_bfloat162 a, b;
        a.x = __float2bfloat16(q0); a.y = __float2bfloat16(q1);
        b.x = __float2bfloat16(q2); b.y = __float2bfloat16(q3);
        dst[2 * i] = a; dst[2 * i + 1] = b;
    }
}

// ---------------- kernel 3: split x into hi/lo bf16 ----------------
__global__ void split_kernel(const float4* __restrict__ x4, int n4) {
    __nv_bfloat162* hi2 = reinterpret_cast<__nv_bfloat162*>(g_xhi);
    __nv_bfloat162* lo2 = reinterpret_cast<__nv_bfloat162*>(g_xlo);
    for (int i = blockIdx.x * blockDim.x + threadIdx.x; i < n4; i += gridDim.x * blockDim.x) {
        float4 v = x4[i];
        __nv_bfloat16 hx = __float2bfloat16(v.x), hy = __float2bfloat16(v.y);
        __nv_bfloat16 hz = __float2bfloat16(v.z), hw = __float2bfloat16(v.w);
        __nv_bfloat162 h01, h23, l01, l23;
        h01.x = hx; h01.y = hy; h23.x = hz; h23.y = hw;
        l01.x = __float2bfloat16(v.x - __bfloat162float(hx));
        l01.y = __float2bfloat16(v.y - __bfloat162float(hy));
        l23.x = __float2bfloat16(v.z - __bfloat162float(hz));
        l23.y = __float2bfloat16(v.w - __bfloat162float(hw));
        hi2[2 * i] = h01; hi2[2 * i + 1] = h23;
        lo2[2 * i] = l01; lo2[2 * i + 1] = l23;
    }
}

// ---------------- kernel 4: HMMA GEMM  out = s_w*(xhi@W'^T + xlo@W'^T) + bias ----------------
// CTA tile 128x128, BK=64, 8 warps (4m x 2n), warp tile 32x64, 2-stage cp.async,
// 2 CTAs/SM, prefetch AFTER compute.
#define BM 128
#define BN 128
#define BK 64
#define PITCH 72                      // bf16 elements per smem row (144 B, conflict-free)
#define MAT_BYTES (128 * PITCH * 2)   // 18432 B per matrix
#define STAGE_BYTES (3 * MAT_BYTES)   // A_hi, A_lo, B = 55296 B
#define NSTAGE 2

__global__ __launch_bounds__(256, 2)
void gemm_tc(const float* __restrict__ bias, int IN, int OUT, int nPer) {
    extern __shared__ char dsm[];
    const uint32_t sb = smem_u32(dsm);
    const int t = threadIdx.x;
    const int wid = t >> 5;
    const int lane = t & 31;
    const int wm = wid & 3;            // 4 m-warps
    const int wn = wid >> 2;           // 2 n-warps
    const int mwarp = wm * 32;
    const int nwarp = wn * 64;
    const int rowbase = blockIdx.y * BM;
    const int colbase = blockIdx.x * BN;
    const int NITER = IN / BK;

    const __nv_bfloat16* xhi = g_xhi;
    const __nv_bfloat16* xlo = g_xlo;
    const __nv_bfloat16* wqb = g_wqb;

    // stage loader: 3072 x 16B chunks (A_hi 1024, A_lo 1024, B 1024), 12 per thread
    auto load_stage = [&](int s, int it) {
        const int k0 = it * BK;
        const uint32_t st = sb + s * STAGE_BYTES;
        #pragma unroll
        for (int j = 0; j < 12; j++) {
            const int m = j >> 2;                 // 0: xhi, 1: xlo, 2: W'
            const int ci = ((j & 3) << 8) + t;    // 0..1023
            const int r = ci >> 3, c = ci & 7;    // r 0..127, c 0..7
            uint32_t dst = st + (uint32_t)(m * MAT_BYTES + r * (PITCH * 2) + c * 16);
            const __nv_bfloat16* src;
            if (m == 0)      src = xhi + (size_t)(rowbase + r) * IN + k0 + c * 8;
            else if (m == 1) src = xlo + (size_t)(rowbase + r) * IN + k0 + c * 8;
            else             src = wqb + (size_t)(colbase + r) * IN + k0 + c * 8;
            cpa16(dst, src);
        }
    };

    // ldmatrix per-thread address components
    const int rowA = lane & 15;                           // row within 16-row tile
    const int kcolA = (lane >> 4) << 3;                   // 0 or 8
    const int rowB = (lane & 7) + ((lane >> 4) & 1) * 8;  // row within 16-row pair of n-tiles
    const int kcolB = ((lane >> 3) & 1) << 3;             // 0 or 8

    float acc[2][8][4];
    #pragma unroll
    for (int i = 0; i < 2; i++)
        #pragma unroll
        for (int j = 0; j < 8; j++)
            #pragma unroll
            for (int e = 0; e < 4; e++) acc[i][j][e] = 0.0f;

    load_stage(0, 0); cpa_commit();
    load_stage(1, 1); cpa_commit();

    for (int it = 0; it < NITER; ++it) {
        const int s = it & 1;
        cpa_wait<1>();
        __syncthreads();
        const uint32_t st = sb + s * STAGE_BYTES;
        #pragma unroll
        for (int kk = 0; kk < 4; kk++) {
            const int kb = kk * 16;
            // B: 8 n-tiles via 4 paired ldmatrix.x4 (2 n-tiles each)
            uint32_t b[8][2];
            #pragma unroll
            for (int np = 0; np < 4; np++) {
                uint32_t addr = st + 2 * MAT_BYTES +
                    (uint32_t)((nwarp + np * 16 + rowB) * (PITCH * 2) + (kb + kcolB) * 2);
                ldsm_x4(b[2 * np][0], b[2 * np][1], b[2 * np + 1][0], b[2 * np + 1][1], addr);
            }
            uint32_t a[2][4];
            // hi
            #pragma unroll
            for (int mt = 0; mt < 2; mt++) {
                uint32_t addr = st +
                    (uint32_t)((mwarp + mt * 16 + rowA) * (PITCH * 2) + (kb + kcolA) * 2);
                ldsm_x4(a[mt][0], a[mt][1], a[mt][2], a[mt][3], addr);
            }
            #pragma unroll
            for (int mt = 0; mt < 2; mt++)
                #pragma unroll
                for (int nt = 0; nt < 8; nt++) mma16816(acc[mt][nt], a[mt], b[nt]);
            // lo
            #pragma unroll
            for (int mt = 0; mt < 2; mt++) {
                uint32_t addr = st + MAT_BYTES +
                    (uint32_t)((mwarp + mt * 16 + rowA) * (PITCH * 2) + (kb + kcolA) * 2);
                ldsm_x4(a[mt][0], a[mt][1], a[mt][2], a[mt][3], addr);
            }
            #pragma unroll
            for (int mt = 0; mt < 2; mt++)
                #pragma unroll
                for (int nt = 0; nt < 8; nt++) mma16816(acc[mt][nt], a[mt], b[nt]);
        }
        __syncthreads();                       // all warps done reading stage s
        if (it + 2 < NITER) load_stage(s, it + 2);
        cpa_commit();
    }

    // ---------------- epilogue ----------------
    const float s_w = g_sw;
    float lmn = INFINITY, lmx = -INFINITY;

    float2 bv[8];
    #pragma unroll
    for (int nt = 0; nt < 8; nt++)
        bv[nt] = *reinterpret_cast<const float2*>(bias + colbase + nwarp + nt * 8 + (lane & 3) * 2);

    #pragma unroll
    for (int mt = 0; mt < 2; mt++) {
        #pragma unroll
        for (int half = 0; half < 2; half++) {
            const int grow = rowbase + mwarp + mt * 16 + (lane >> 2) + half * 8;
            float* dstrow = g_out + (size_t)grow * OUT + colbase + nwarp + (lane & 3) * 2;
            #pragma unroll
            for (int nt = 0; nt < 8; nt++) {
                float v0 = fmaf(s_w, acc[mt][nt][half * 2 + 0], bv[nt].x);
                float v1 = fmaf(s_w, acc[mt][nt][half * 2 + 1], bv[nt].y);
                lmn = fminf(lmn, fminf(v0, v1));
                lmx = fmaxf(lmx, fmaxf(v0, v1));
                *reinterpret_cast<float2*>(dstrow + nt * 8) = make_float2(v0, v1);
            }
        }
    }

    #pragma unroll
    for (int o = 16; o; o >>= 1) {
        lmn = fminf(lmn, __shfl_xor_sync(0xffffffffu, lmn, o));
        lmx = fmaxf(lmx, __shfl_xor_sync(0xffffffffu, lmx, o));
    }
    __shared__ float rmn[8], rmx[8];
    if (lane == 0) { rmn[wid] = lmn; rmx[wid] = lmx; }
    __syncthreads();
    if (t == 0) {
        for (int i = 1; i < 8; i++) { lmn = fminf(lmn, rmn[i]); lmx = fmaxf(lmx, rmx[i]); }
        int cl = rowbase / nPer;
        atomicMin(&g_cmin[cl], f2o(lmn));
        atomicMax(&g_cmax[cl], f2o(lmx));
    }
}

// ---------------- kernel 5: EMA range update + qparams ----------------
__global__ void range_kernel(const float* __restrict__ act_range, const int* __restrict__ cinfo,
                             float* __restrict__ out_range, int K) {
    int t = threadIdx.x;
    if (t < K) {
        out_range[2 * t]     = act_range[2 * t];
        out_range[2 * t + 1] = act_range[2 * t + 1];
    }
    __syncthreads();
    if (t < K) {
        float mn = o2f(g_cmin[t]), mx = o2f(g_cmax[t]);
        int c = cinfo[2 * t];
        float o0 = act_range[2 * c], o1 = act_range[2 * c + 1];
        float nmin = __fadd_rn(__fmul_rn(o0, 0.999f), __fmul_rn(mn, 0.001f));
        float nmax = __fadd_rn(__fmul_rn(o1, 0.999f), __fmul_rn(mx, 0.001f));
        out_range[2 * c]     = nmin;
        out_range[2 * c + 1] = nmax;
        float s = __fdiv_rn(__fsub_rn(nmax, nmin), 255.0f);
        g_s3[t] = s;
        g_z3[t] = -rintf(__fdiv_rn(nmin, s));
    }
}

// ---------------- kernel 6: fake-quantize GEMM output ----------------
__global__ void quantout_kernel(float4* __restrict__ outq, int n4, int shift) {
    const float4* src = reinterpret_cast<const float4*>(g_out);
    for (int i = blockIdx.x * blockDim.x + threadIdx.x; i < n4; i += gridDim.x * blockDim.x) {
        int k = i >> shift;
        float s = g_s3[k], z = g_z3[k];
        float4 v = src[i];
        v.x = fq(v.x, s, z); v.y = fq(v.y, s, z);
        v.z = fq(v.z, s, z); v.w = fq(v.w, s, z);
        outq[i] = v;
    }
}
// fallback when chunk4 is not a power of two
__global__ void quantout_div_kernel(float4* __restrict__ outq, int n4, int chunk4) {
    const float4* src = reinterpret_cast<const float4*>(g_out);
    for (int i = blockIdx.x * blockDim.x + threadIdx.x; i < n4; i += gridDim.x * blockDim.x) {
        int k = i / chunk4;
        float s = g_s3[k], z = g_z3[k];
        float4 v = src[i];
        v.x = fq(v.x, s, z); v.y = fq(v.y, s, z);
        v.z = fq(v.z, s, z); v.w = fq(v.w, s, z);
        outq[i] = v;
    }
}

// ---------------- launch ----------------
extern "C" void kernel_launch(void* const* d_in, const int* in_sizes, int n_in,
                              void* d_out, int out_size) {
    const float* x         = (const float*)d_in[0];
    const float* w         = (const float*)d_in[1];
    const float* bias      = (const float*)d_in[2];
    const float* act_range = (const float*)d_in[3];
    const int*   cinfo     = (const int*)d_in[4];

    const int OUT = in_sizes[2];
    const int IN  = in_sizes[1] / OUT;
    const int B   = in_sizes[0] / IN;
    const int K   = in_sizes[3] / 2;
    const int n   = B / K;

    float* outq      = (float*)d_out;
    float* out_range = outq + (size_t)B * OUT;

    const int smem_bytes = NSTAGE * STAGE_BYTES;   // 110592
    cudaFuncSetAttribute(gemm_tc, cudaFuncAttributeMaxDynamicSharedMemorySize, smem_bytes);

    init_kernel<<<1, 32>>>();

    const int wn4 = (OUT * IN) / 4;
    wminmax_kernel<<<512, 256>>>((const float4*)w, wn4);
    quantw_kernel<<<2048, 256>>>((const float4*)w, wn4);

    const int xn4 = (B * IN) / 4;
    split_kernel<<<2048, 256>>>((const float4*)x, xn4);

    dim3 grid(OUT / BN, B / BM);
    gemm_tc<<<grid, 256, smem_bytes>>>(bias, IN, OUT, n);

    range_kernel<<<1, 32>>>(act_range, cinfo, out_range, K);

    const int on4 = (B / 4) * OUT;
    const int chunk4 = (n * OUT) / 4;
    if ((chunk4 & (chunk4 - 1)) == 0) {
        int shift = 0;
        while ((1 << shift) < chunk4) shift++;
        quantout_kernel<<<2048, 256>>>((float4*)outq, on4, shift);
    } else {
        quantout_div_kernel<<<2048, 256>>>((float4*)outq, on4, chunk4);
    }
}

// round 15
// speedup vs baseline: 1.0099x; 1.0099x over previous
#include <cuda_runtime.h>
#include <cuda_bf16.h>
#include <math.h>
#include <stdint.h>

// ---------------- static scratch ----------------
static __device__ __nv_bfloat16 g_wqb[4096u * 4096u];   // W' = q - z (exact ints in bf16)
static __device__ __nv_bfloat16 g_xhi[10240u * 4096u];  // bf16 hi part of x
static __device__ __nv_bfloat16 g_xlo[10240u * 4096u];  // bf16 lo residual of x
static __device__ float g_out[10240u * 4096u];          // pre-quant GEMM output
__device__ unsigned g_wmm[2];
__device__ unsigned g_cmin[32], g_cmax[32];
__device__ float g_s3[32], g_z3[32];
__device__ float g_sw;

// ---- monotone float <-> uint encoding ----
__device__ __forceinline__ unsigned f2o(float f) {
    unsigned u = __float_as_uint(f);
    return (u & 0x80000000u) ? ~u : (u | 0x80000000u);
}
__device__ __forceinline__ float o2f(unsigned u) {
    unsigned v = (u & 0x80000000u) ? (u ^ 0x80000000u) : ~u;
    return __uint_as_float(v);
}
__device__ __forceinline__ float fq(float v, float s, float z) {
    float q = rintf(__fadd_rn(__fdiv_rn(v, s), z));
    q = fminf(fmaxf(q, 0.0f), 255.0f);
    return __fmul_rn(__fsub_rn(q, z), s);
}

// ---------------- PTX helpers ----------------
__device__ __forceinline__ uint32_t smem_u32(const void* p) {
    uint32_t a;
    asm("{ .reg .u64 t; cvta.to.shared.u64 t, %1; cvt.u32.u64 %0, t; }" : "=r"(a) : "l"(p));
    return a;
}
__device__ __forceinline__ void cpa16(uint32_t d, const void* s) {
    asm volatile("cp.async.cg.shared.global [%0], [%1], 16;" :: "r"(d), "l"(s));
}
__device__ __forceinline__ void cpa_commit() { asm volatile("cp.async.commit_group;" ::: "memory"); }
template<int N> __device__ __forceinline__ void cpa_wait() {
    asm volatile("cp.async.wait_group %0;" :: "n"(N) : "memory");
}
__device__ __forceinline__ void ldsm_x4(uint32_t& r0, uint32_t& r1, uint32_t& r2, uint32_t& r3,
                                        uint32_t addr) {
    asm volatile("ldmatrix.sync.aligned.m8n8.x4.shared.b16 {%0,%1,%2,%3}, [%4];"
                 : "=r"(r0), "=r"(r1), "=r"(r2), "=r"(r3) : "r"(addr));
}
__device__ __forceinline__ void mma16816(float* c, const uint32_t* a, const uint32_t* b) {
    asm volatile("mma.sync.aligned.m16n8k16.row.col.f32.bf16.bf16.f32 "
                 "{%0,%1,%2,%3}, {%4,%5,%6,%7}, {%8,%9}, {%0,%1,%2,%3};"
                 : "+f"(c[0]), "+f"(c[1]), "+f"(c[2]), "+f"(c[3])
                 : "r"(a[0]), "r"(a[1]), "r"(a[2]), "r"(a[3]), "r"(b[0]), "r"(b[1]));
}

// ---------------- kernel 0: reset reduction state ----------------
__global__ void init_kernel() {
    if (threadIdx.x == 0) { g_wmm[0] = 0xFFFFFFFFu; g_wmm[1] = 0u; }
    if (threadIdx.x < 32) { g_cmin[threadIdx.x] = 0xFFFFFFFFu; g_cmax[threadIdx.x] = 0u; }
}

// ---------------- kernel 1: weight min/max ----------------
__global__ void wminmax_kernel(const float4* __restrict__ w4, int n4) {
    float mn = INFINITY, mx = -INFINITY;
    for (int i = blockIdx.x * blockDim.x + threadIdx.x; i < n4; i += gridDim.x * blockDim.x) {
        float4 v = w4[i];
        mn = fminf(mn, fminf(fminf(v.x, v.y), fminf(v.z, v.w)));
        mx = fmaxf(mx, fmaxf(fmaxf(v.x, v.y), fmaxf(v.z, v.w)));
    }
    #pragma unroll
    for (int o = 16; o; o >>= 1) {
        mn = fminf(mn, __shfl_xor_sync(0xffffffffu, mn, o));
        mx = fmaxf(mx, __shfl_xor_sync(0xffffffffu, mx, o));
    }
    __shared__ float smn[8], smx[8];
    if ((threadIdx.x & 31) == 0) { smn[threadIdx.x >> 5] = mn; smx[threadIdx.x >> 5] = mx; }
    __syncthreads();
    if (threadIdx.x == 0) {
        for (int i = 1; i < (int)(blockDim.x >> 5); i++) { mn = fminf(mn, smn[i]); mx = fmaxf(mx, smx[i]); }
        atomicMin(&g_wmm[0], f2o(mn));
        atomicMax(&g_wmm[1], f2o(mx));
    }
}

// ---------------- kernel 2: W' = q - z into bf16 (exact) ----------------
__global__ void quantw_kernel(const float4* __restrict__ w4, int n4) {
    float mn = o2f(g_wmm[0]), mx = o2f(g_wmm[1]);
    float s = __fdiv_rn(__fsub_rn(mx, mn), 255.0f);
    float z = -rintf(__fdiv_rn(mn, s));
    if (blockIdx.x == 0 && threadIdx.x == 0) g_sw = s;
    __nv_bfloat162* dst = reinterpret_cast<__nv_bfloat162*>(g_wqb);
    for (int i = blockIdx.x * blockDim.x + threadIdx.x; i < n4; i += gridDim.x * blockDim.x) {
        float4 v = w4[i];
        float q0 = fminf(fmaxf(rintf(__fadd_rn(__fdiv_rn(v.x, s), z)), 0.f), 255.f) - z;
        float q1 = fminf(fmaxf(rintf(__fadd_rn(__fdiv_rn(v.y, s), z)), 0.f), 255.f) - z;
        float q2 = fminf(fmaxf(rintf(__fadd_rn(__fdiv_rn(v.z, s), z)), 0.f), 255.f) - z;
        float q3 = fminf(fmaxf(rintf(__fadd_rn(__fdiv_rn(v.w, s), z)), 0.f), 255.f) - z;
        __nv_bfloat162 a, b;
        a.x = __float2bfloat16(q0); a.y = __float2bfloat16(q1);
        b.x = __float2bfloat16(q2); b.y = __float2bfloat16(q3);
        dst[2 * i] = a; dst[2 * i + 1] = b;
    }
}

// ---------------- kernel 3: split x into hi/lo bf16 ----------------
__global__ void split_kernel(const float4* __restrict__ x4, int n4) {
    __nv_bfloat162* hi2 = reinterpret_cast<__nv_bfloat162*>(g_xhi);
    __nv_bfloat162* lo2 = reinterpret_cast<__nv_bfloat162*>(g_xlo);
    for (int i = blockIdx.x * blockDim.x + threadIdx.x; i < n4; i += gridDim.x * blockDim.x) {
        float4 v = x4[i];
        __nv_bfloat16 hx = __float2bfloat16(v.x), hy = __float2bfloat16(v.y);
        __nv_bfloat16 hz = __float2bfloat16(v.z), hw = __float2bfloat16(v.w);
        __nv_bfloat162 h01, h23, l01, l23;
        h01.x = hx; h01.y = hy; h23.x = hz; h23.y = hw;
        l01.x = __float2bfloat16(v.x - __bfloat162float(hx));
        l01.y = __float2bfloat16(v.y - __bfloat162float(hy));
        l23.x = __float2bfloat16(v.z - __bfloat162float(hz));
        l23.y = __float2bfloat16(v.w - __bfloat162float(hw));
        hi2[2 * i] = h01; hi2[2 * i + 1] = h23;
        lo2[2 * i] = l01; lo2[2 * i + 1] = l23;
    }
}

// ---------------- kernel 4: HMMA GEMM  out = s_w*(xhi@W'^T + xlo@W'^T) + bias ----------------
// CTA tile 128x256, BK=32, 16 warps (4m x 4n), warp tile 32x64, 3-stage cp.async,
// 512 threads, 1 CTA/SM (16 warps/SM), prefetch AFTER compute.
#define BM 128
#define BN 256
#define BK 32
#define PITCH 40                       // bf16 elements per smem row (80 B, conflict-free)
#define A_BYTES (128 * PITCH * 2)      // 10240 B per A matrix (hi or lo)
#define B_BYTES (256 * PITCH * 2)      // 20480 B
#define STAGE_BYTES (2 * A_BYTES + B_BYTES)  // 40960 B
#define NSTAGE 3
#define NTHREADS 512

__global__ __launch_bounds__(NTHREADS, 1)
void gemm_tc(const float* __restrict__ bias, int IN, int OUT, int nPer) {
    extern __shared__ char dsm[];
    const uint32_t sb = smem_u32(dsm);
    const int t = threadIdx.x;
    const int wid = t >> 5;
    const int lane = t & 31;
    const int wm = wid & 3;            // 4 m-warps
    const int wn = wid >> 2;           // 4 n-warps
    const int mwarp = wm * 32;
    const int nwarp = wn * 64;
    const int rowbase = blockIdx.y * BM;
    const int colbase = blockIdx.x * BN;
    const int NITER = IN / BK;

    const __nv_bfloat16* xhi = g_xhi;
    const __nv_bfloat16* xlo = g_xlo;
    const __nv_bfloat16* wqb = g_wqb;

    // stage loader: 2048 x 16B chunks (A_hi 512, A_lo 512, B 1024), 4 per thread
    auto load_stage = [&](int s, int it) {
        const int k0 = it * BK;
        const uint32_t st = sb + s * STAGE_BYTES;
        #pragma unroll
        for (int j = 0; j < 4; j++) {
            const int ci = j * NTHREADS + t;      // 0..2047
            if (ci < 1024) {                      // A: hi (0..511), lo (512..1023)
                const int m = ci >= 512;
                const int cia = ci - m * 512;     // 0..511
                const int r = cia >> 2, c = cia & 3;  // r 0..127
                uint32_t dst = st + (uint32_t)(m * A_BYTES + r * (PITCH * 2) + c * 16);
                const __nv_bfloat16* src = (m ? xlo : xhi) + (size_t)(rowbase + r) * IN + k0 + c * 8;
                cpa16(dst, src);
            } else {                              // B: 1024 chunks, 256 rows
                const int cib = ci - 1024;        // 0..1023
                const int r = cib >> 2, c = cib & 3;  // r 0..255
                uint32_t dst = st + (uint32_t)(2 * A_BYTES + r * (PITCH * 2) + c * 16);
                cpa16(dst, wqb + (size_t)(colbase + r) * IN + k0 + c * 8);
            }
        }
    };

    // ldmatrix per-thread address components
    const int rowA = lane & 15;                           // row within 16-row tile
    const int kcolA = (lane >> 4) << 3;                   // 0 or 8
    const int rowB = (lane & 7) + ((lane >> 4) & 1) * 8;  // row within 16-row pair of n-tiles
    const int kcolB = ((lane >> 3) & 1) << 3;             // 0 or 8

    float acc[2][8][4];
    #pragma unroll
    for (int i = 0; i < 2; i++)
        #pragma unroll
        for (int j = 0; j < 8; j++)
            #pragma unroll
            for (int e = 0; e < 4; e++) acc[i][j][e] = 0.0f;

    load_stage(0, 0); cpa_commit();
    load_stage(1, 1); cpa_commit();

    for (int it = 0; it < NITER; ++it) {
        const int s = it % NSTAGE;
        cpa_wait<1>();
        __syncthreads();
        const uint32_t st = sb + s * STAGE_BYTES;
        #pragma unroll
        for (int kk = 0; kk < 2; kk++) {
            const int kb = kk * 16;
            // B: 8 n-tiles via 4 paired ldmatrix.x4 (2 n-tiles each)
            uint32_t b[8][2];
            #pragma unroll
            for (int np = 0; np < 4; np++) {
                uint32_t addr = st + 2 * A_BYTES +
                    (uint32_t)((nwarp + np * 16 + rowB) * (PITCH * 2) + (kb + kcolB) * 2);
                ldsm_x4(b[2 * np][0], b[2 * np][1], b[2 * np + 1][0], b[2 * np + 1][1], addr);
            }
            uint32_t a[2][4];
            // hi
            #pragma unroll
            for (int mt = 0; mt < 2; mt++) {
                uint32_t addr = st +
                    (uint32_t)((mwarp + mt * 16 + rowA) * (PITCH * 2) + (kb + kcolA) * 2);
                ldsm_x4(a[mt][0], a[mt][1], a[mt][2], a[mt][3], addr);
            }
            #pragma unroll
            for (int mt = 0; mt < 2; mt++)
                #pragma unroll
                for (int nt = 0; nt < 8; nt++) mma16816(acc[mt][nt], a[mt], b[nt]);
            // lo
            #pragma unroll
            for (int mt = 0; mt < 2; mt++) {
                uint32_t addr = st + A_BYTES +
                    (uint32_t)((mwarp + mt * 16 + rowA) * (PITCH * 2) + (kb + kcolA) * 2);
                ldsm_x4(a[mt][0], a[mt][1], a[mt][2], a[mt][3], addr);
            }
            #pragma unroll
            for (int mt = 0; mt < 2; mt++)
                #pragma unroll
                for (int nt = 0; nt < 8; nt++) mma16816(acc[mt][nt], a[mt], b[nt]);
        }
        if (it + 2 < NITER) load_stage((it + 2) % NSTAGE, it + 2);
        cpa_commit();
    }

    // ---------------- epilogue ----------------
    const float s_w = g_sw;
    float lmn = INFINITY, lmx = -INFINITY;

    float2 bv[8];
    #pragma unroll
    for (int nt = 0; nt < 8; nt++)
        bv[nt] = *reinterpret_cast<const float2*>(bias + colbase + nwarp + nt * 8 + (lane & 3) * 2);

    #pragma unroll
    for (int mt = 0; mt < 2; mt++) {
        #pragma unroll
        for (int half = 0; half < 2; half++) {
            const int grow = rowbase + mwarp + mt * 16 + (lane >> 2) + half * 8;
            float* dstrow = g_out + (size_t)grow * OUT + colbase + nwarp + (lane & 3) * 2;
            #pragma unroll
            for (int nt = 0; nt < 8; nt++) {
                float v0 = fmaf(s_w, acc[mt][nt][half * 2 + 0], bv[nt].x);
                float v1 = fmaf(s_w, acc[mt][nt][half * 2 + 1], bv[nt].y);
                lmn = fminf(lmn, fminf(v0, v1));
                lmx = fmaxf(lmx, fmaxf(v0, v1));
                *reinterpret_cast<float2*>(dstrow + nt * 8) = make_float2(v0, v1);
            }
        }
    }

    #pragma unroll
    for (int o = 16; o; o >>= 1) {
        lmn = fminf(lmn, __shfl_xor_sync(0xffffffffu, lmn, o));
        lmx = fmaxf(lmx, __shfl_xor_sync(0xffffffffu, lmx, o));
    }
    __shared__ float rmn[16], rmx[16];
    if (lane == 0) { rmn[wid] = lmn; rmx[wid] = lmx; }
    __syncthreads();
    if (t == 0) {
        for (int i = 1; i < 16; i++) { lmn = fminf(lmn, rmn[i]); lmx = fmaxf(lmx, rmx[i]); }
        int cl = rowbase / nPer;
        atomicMin(&g_cmin[cl], f2o(lmn));
        atomicMax(&g_cmax[cl], f2o(lmx));
    }
}

// ---------------- kernel 5: EMA range update + qparams ----------------
__global__ void range_kernel(const float* __restrict__ act_range, const int* __restrict__ cinfo,
                             float* __restrict__ out_range, int K) {
    int t = threadIdx.x;
    if (t < K) {
        out_range[2 * t]     = act_range[2 * t];
        out_range[2 * t + 1] = act_range[2 * t + 1];
    }
    __syncthreads();
    if (t < K) {
        float mn = o2f(g_cmin[t]), mx = o2f(g_cmax[t]);
        int c = cinfo[2 * t];
        float o0 = act_range[2 * c], o1 = act_range[2 * c + 1];
        float nmin = __fadd_rn(__fmul_rn(o0, 0.999f), __fmul_rn(mn, 0.001f));
        float nmax = __fadd_rn(__fmul_rn(o1, 0.999f), __fmul_rn(mx, 0.001f));
        out_range[2 * c]     = nmin;
        out_range[2 * c + 1] = nmax;
        float s = __fdiv_rn(__fsub_rn(nmax, nmin), 255.0f);
        g_s3[t] = s;
        g_z3[t] = -rintf(__fdiv_rn(nmin, s));
    }
}

// ---------------- kernel 6: fake-quantize GEMM output ----------------
__global__ void quantout_kernel(float4* __restrict__ outq, int n4, int shift) {
    const float4* src = reinterpret_cast<const float4*>(g_out);
    for (int i = blockIdx.x * blockDim.x + threadIdx.x; i < n4; i += gridDim.x * blockDim.x) {
        int k = i >> shift;
        float s = g_s3[k], z = g_z3[k];
        float4 v = src[i];
        v.x = fq(v.x, s, z); v.y = fq(v.y, s, z);
        v.z = fq(v.z, s, z); v.w = fq(v.w, s, z);
        outq[i] = v;
    }
}
// fallback when chunk4 is not a power of two
__global__ void quantout_div_kernel(float4* __restrict__ outq, int n4, int chunk4) {
    const float4* src = reinterpret_cast<const float4*>(g_out);
    for (int i = blockIdx.x * blockDim.x + threadIdx.x; i < n4; i += gridDim.x * blockDim.x) {
        int k = i / chunk4;
        float s = g_s3[k], z = g_z3[k];
        float4 v = src[i];
        v.x = fq(v.x, s, z); v.y = fq(v.y, s, z);
        v.z = fq(v.z, s, z); v.w = fq(v.w, s, z);
        outq[i] = v;
    }
}

// ---------------- launch ----------------
extern "C" void kernel_launch(void* const* d_in, const int* in_sizes, int n_in,
                              void* d_out, int out_size) {
    const float* x         = (const float*)d_in[0];
    const float* w         = (const float*)d_in[1];
    const float* bias      = (const float*)d_in[2];
    const float* act_range = (const float*)d_in[3];
    const int*   cinfo     = (const int*)d_in[4];

    const int OUT = in_sizes[2];
    const int IN  = in_sizes[1] / OUT;
    const int B   = in_sizes[0] / IN;
    const int K   = in_sizes[3] / 2;
    const int n   = B / K;

    float* outq      = (float*)d_out;
    float* out_range = outq + (size_t)B * OUT;

    const int smem_bytes = NSTAGE * STAGE_BYTES;   // 122880
    cudaFuncSetAttribute(gemm_tc, cudaFuncAttributeMaxDynamicSharedMemorySize, smem_bytes);

    init_kernel<<<1, 32>>>();

    const int wn4 = (OUT * IN) / 4;
    wminmax_kernel<<<512, 256>>>((const float4*)w, wn4);
    quantw_kernel<<<2048, 256>>>((const float4*)w, wn4);

    const int xn4 = (B * IN) / 4;
    split_kernel<<<2048, 256>>>((const float4*)x, xn4);

    dim3 grid(OUT / BN, B / BM);
    gemm_tc<<<grid, NTHREADS, smem_bytes>>>(bias, IN, OUT, n);

    range_kernel<<<1, 32>>>(act_range, cinfo, out_range, K);

    const int on4 = (B / 4) * OUT;
    const int chunk4 = (n * OUT) / 4;
    if ((chunk4 & (chunk4 - 1)) == 0) {
        int shift = 0;
        while ((1 << shift) < chunk4) shift++;
        quantout_kernel<<<2048, 256>>>((float4*)outq, on4, shift);
    } else {
        quantout_div_kernel<<<2048, 256>>>((float4*)outq, on4, chunk4);
    }
}

// round 16
// speedup vs baseline: 1.0674x; 1.0569x over previous
#include <cuda_runtime.h>
#include <cuda_bf16.h>
#include <math.h>
#include <stdint.h>

// ---------------- static scratch ----------------
static __device__ __nv_bfloat16 g_wqb[4096u * 4096u];   // W' = q - z (exact ints in bf16)
static __device__ __nv_bfloat16 g_xhi[10240u * 4096u];  // bf16 hi part of x
static __device__ __nv_bfloat16 g_xlo[10240u * 4096u];  // bf16 lo residual of x
static __device__ float g_out[10240u * 4096u];          // pre-quant GEMM output
__device__ unsigned g_wmm[2];
__device__ unsigned g_cmin[32], g_cmax[32];
__device__ float g_s3[32], g_z3[32];
__device__ float g_sw;

// ---- monotone float <-> uint encoding ----
__device__ __forceinline__ unsigned f2o(float f) {
    unsigned u = __float_as_uint(f);
    return (u & 0x80000000u) ? ~u : (u | 0x80000000u);
}
__device__ __forceinline__ float o2f(unsigned u) {
    unsigned v = (u & 0x80000000u) ? (u ^ 0x80000000u) : ~u;
    return __uint_as_float(v);
}
__device__ __forceinline__ float fq(float v, float s, float z) {
    float q = rintf(__fadd_rn(__fdiv_rn(v, s), z));
    q = fminf(fmaxf(q, 0.0f), 255.0f);
    return __fmul_rn(__fsub_rn(q, z), s);
}

// ---------------- PTX helpers ----------------
__device__ __forceinline__ uint32_t smem_u32(const void* p) {
    uint32_t a;
    asm("{ .reg .u64 t; cvta.to.shared.u64 t, %1; cvt.u32.u64 %0, t; }" : "=r"(a) : "l"(p));
    return a;
}
__device__ __forceinline__ void cpa16(uint32_t d, const void* s) {
    asm volatile("cp.async.cg.shared.global [%0], [%1], 16;" :: "r"(d), "l"(s));
}
__device__ __forceinline__ void cpa_commit() { asm volatile("cp.async.commit_group;" ::: "memory"); }
template<int N> __device__ __forceinline__ void cpa_wait() {
    asm volatile("cp.async.wait_group %0;" :: "n"(N) : "memory");
}
__device__ __forceinline__ void ldsm_x4(uint32_t& r0, uint32_t& r1, uint32_t& r2, uint32_t& r3,
                                        uint32_t addr) {
    asm volatile("ldmatrix.sync.aligned.m8n8.x4.shared.b16 {%0,%1,%2,%3}, [%4];"
                 : "=r"(r0), "=r"(r1), "=r"(r2), "=r"(r3) : "r"(addr));
}
__device__ __forceinline__ void mma16816(float* c, const uint32_t* a, const uint32_t* b) {
    asm volatile("mma.sync.aligned.m16n8k16.row.col.f32.bf16.bf16.f32 "
                 "{%0,%1,%2,%3}, {%4,%5,%6,%7}, {%8,%9}, {%0,%1,%2,%3};"
                 : "+f"(c[0]), "+f"(c[1]), "+f"(c[2]), "+f"(c[3])
                 : "r"(a[0]), "r"(a[1]), "r"(a[2]), "r"(a[3]), "r"(b[0]), "r"(b[1]));
}
__device__ __forceinline__ uint32_t pack_bf16x2(float lo, float hi) {
    __nv_bfloat162 p;
    p.x = __float2bfloat16(lo);
    p.y = __float2bfloat16(hi);
    return *reinterpret_cast<uint32_t*>(&p);
}

// ---------------- kernel 0: reset reduction state ----------------
__global__ void init_kernel() {
    if (threadIdx.x == 0) { g_wmm[0] = 0xFFFFFFFFu; g_wmm[1] = 0u; }
    if (threadIdx.x < 32) { g_cmin[threadIdx.x] = 0xFFFFFFFFu; g_cmax[threadIdx.x] = 0u; }
}

// ---------------- kernel 1: weight min/max ----------------
__global__ void wminmax_kernel(const float4* __restrict__ w4, int n4) {
    float mn = INFINITY, mx = -INFINITY;
    for (int i = blockIdx.x * blockDim.x + threadIdx.x; i < n4; i += gridDim.x * blockDim.x) {
        float4 v = w4[i];
        mn = fminf(mn, fminf(fminf(v.x, v.y), fminf(v.z, v.w)));
        mx = fmaxf(mx, fmaxf(fmaxf(v.x, v.y), fmaxf(v.z, v.w)));
    }
    #pragma unroll
    for (int o = 16; o; o >>= 1) {
        mn = fminf(mn, __shfl_xor_sync(0xffffffffu, mn, o));
        mx = fmaxf(mx, __shfl_xor_sync(0xffffffffu, mx, o));
    }
    __shared__ float smn[8], smx[8];
    if ((threadIdx.x & 31) == 0) { smn[threadIdx.x >> 5] = mn; smx[threadIdx.x >> 5] = mx; }
    __syncthreads();
    if (threadIdx.x == 0) {
        for (int i = 1; i < (int)(blockDim.x >> 5); i++) { mn = fminf(mn, smn[i]); mx = fmaxf(mx, smx[i]); }
        atomicMin(&g_wmm[0], f2o(mn));
        atomicMax(&g_wmm[1], f2o(mx));
    }
}

// ---------------- kernel 2: W' = q - z into bf16, vectorized 16B stores ----------------
__global__ void quantw_kernel(const float4* __restrict__ w4, int n8) {
    float mn = o2f(g_wmm[0]), mx = o2f(g_wmm[1]);
    float s = __fdiv_rn(__fsub_rn(mx, mn), 255.0f);
    float z = -rintf(__fdiv_rn(mn, s));
    if (blockIdx.x == 0 && threadIdx.x == 0) g_sw = s;
    uint4* dst = reinterpret_cast<uint4*>(g_wqb);
    for (int i = blockIdx.x * blockDim.x + threadIdx.x; i < n8; i += gridDim.x * blockDim.x) {
        float4 v0 = w4[2 * i];
        float4 v1 = w4[2 * i + 1];
        float e[8] = {v0.x, v0.y, v0.z, v0.w, v1.x, v1.y, v1.z, v1.w};
        float q[8];
        #pragma unroll
        for (int j = 0; j < 8; j++)
            q[j] = fminf(fmaxf(rintf(__fadd_rn(__fdiv_rn(e[j], s), z)), 0.f), 255.f) - z;
        uint4 o;
        o.x = pack_bf16x2(q[0], q[1]);
        o.y = pack_bf16x2(q[2], q[3]);
        o.z = pack_bf16x2(q[4], q[5]);
        o.w = pack_bf16x2(q[6], q[7]);
        dst[i] = o;
    }
}

// ---------------- kernel 3: split x into hi/lo bf16, vectorized 16B stores ----------------
__global__ void split_kernel(const float4* __restrict__ x4, int n8) {
    uint4* hi4 = reinterpret_cast<uint4*>(g_xhi);
    uint4* lo4 = reinterpret_cast<uint4*>(g_xlo);
    for (int i = blockIdx.x * blockDim.x + threadIdx.x; i < n8; i += gridDim.x * blockDim.x) {
        float4 v0 = x4[2 * i];
        float4 v1 = x4[2 * i + 1];
        float e[8] = {v0.x, v0.y, v0.z, v0.w, v1.x, v1.y, v1.z, v1.w};
        float h[8], l[8];
        #pragma unroll
        for (int j = 0; j < 8; j++) {
            __nv_bfloat16 hb = __float2bfloat16(e[j]);
            h[j] = __bfloat162float(hb);
            l[j] = e[j] - h[j];
        }
        uint4 oh, ol;
        oh.x = pack_bf16x2(h[0], h[1]); oh.y = pack_bf16x2(h[2], h[3]);
        oh.z = pack_bf16x2(h[4], h[5]); oh.w = pack_bf16x2(h[6], h[7]);
        ol.x = pack_bf16x2(l[0], l[1]); ol.y = pack_bf16x2(l[2], l[3]);
        ol.z = pack_bf16x2(l[4], l[5]); ol.w = pack_bf16x2(l[6], l[7]);
        hi4[i] = oh;
        lo4[i] = ol;
    }
}

// ---------------- kernel 4: HMMA GEMM  out = s_w*(xhi@W'^T + xlo@W'^T) + bias ----------------
// CTA tile 128x128, BK=32, 8 warps (4m x 2n), warp tile 32x64, 3-stage cp.async,
// 2 CTAs/SM, prefetch AFTER compute (round-12 configuration — empirical best).
#define BM 128
#define BN 128
#define BK 32
#define PITCH 40                      // bf16 elements per smem row (80 B, conflict-free)
#define MAT_BYTES (128 * PITCH * 2)   // 10240 B per matrix
#define STAGE_BYTES (3 * MAT_BYTES)   // A_hi, A_lo, B
#define NSTAGE 3

__global__ __launch_bounds__(256, 2)
void gemm_tc(const float* __restrict__ bias, int IN, int OUT, int nPer) {
    extern __shared__ char dsm[];
    const uint32_t sb = smem_u32(dsm);
    const int t = threadIdx.x;
    const int wid = t >> 5;
    const int lane = t & 31;
    const int wm = wid & 3;            // 4 m-warps
    const int wn = wid >> 2;           // 2 n-warps
    const int mwarp = wm * 32;
    const int nwarp = wn * 64;
    const int rowbase = blockIdx.y * BM;
    const int colbase = blockIdx.x * BN;
    const int NITER = IN / BK;

    const __nv_bfloat16* xhi = g_xhi;
    const __nv_bfloat16* xlo = g_xlo;
    const __nv_bfloat16* wqb = g_wqb;

    // stage loader: 1536 x 16B chunks (A_hi 512, A_lo 512, B 512), 6 per thread
    auto load_stage = [&](int s, int it) {
        const int k0 = it * BK;
        const uint32_t st = sb + s * STAGE_BYTES;
        #pragma unroll
        for (int j = 0; j < 6; j++) {
            const int m = j >> 1;                 // 0: xhi, 1: xlo, 2: W'
            const int ci = ((j & 1) << 8) + t;    // 0..511
            const int r = ci >> 2, c = ci & 3;
            uint32_t dst = st + (uint32_t)(m * MAT_BYTES + r * (PITCH * 2) + c * 16);
            const __nv_bfloat16* src;
            if (m == 0)      src = xhi + (size_t)(rowbase + r) * IN + k0 + c * 8;
            else if (m == 1) src = xlo + (size_t)(rowbase + r) * IN + k0 + c * 8;
            else             src = wqb + (size_t)(colbase + r) * IN + k0 + c * 8;
            cpa16(dst, src);
        }
    };

    // ldmatrix per-thread address components
    const int rowA = lane & 15;                           // row within 16-row tile
    const int kcolA = (lane >> 4) << 3;                   // 0 or 8
    const int rowB = (lane & 7) + ((lane >> 4) & 1) * 8;  // row within 16-row pair of n-tiles
    const int kcolB = ((lane >> 3) & 1) << 3;             // 0 or 8

    float acc[2][8][4];
    #pragma unroll
    for (int i = 0; i < 2; i++)
        #pragma unroll
        for (int j = 0; j < 8; j++)
            #pragma unroll
            for (int e = 0; e < 4; e++) acc[i][j][e] = 0.0f;

    load_stage(0, 0); cpa_commit();
    load_stage(1, 1); cpa_commit();

    for (int it = 0; it < NITER; ++it) {
        const int s = it % NSTAGE;
        cpa_wait<1>();
        __syncthreads();
        const uint32_t st = sb + s * STAGE_BYTES;
        #pragma unroll
        for (int kk = 0; kk < 2; kk++) {
            const int kb = kk * 16;
            // B: 8 n-tiles via 4 paired ldmatrix.x4 (2 n-tiles each)
            uint32_t b[8][2];
            #pragma unroll
            for (int np = 0; np < 4; np++) {
                uint32_t addr = st + 2 * MAT_BYTES +
                    (uint32_t)((nwarp + np * 16 + rowB) * (PITCH * 2) + (kb + kcolB) * 2);
                ldsm_x4(b[2 * np][0], b[2 * np][1], b[2 * np + 1][0], b[2 * np + 1][1], addr);
            }
            uint32_t a[2][4];
            // hi
            #pragma unroll
            for (int mt = 0; mt < 2; mt++) {
                uint32_t addr = st +
                    (uint32_t)((mwarp + mt * 16 + rowA) * (PITCH * 2) + (kb + kcolA) * 2);
                ldsm_x4(a[mt][0], a[mt][1], a[mt][2], a[mt][3], addr);
            }
            #pragma unroll
            for (int mt = 0; mt < 2; mt++)
                #pragma unroll
                for (int nt = 0; nt < 8; nt++) mma16816(acc[mt][nt], a[mt], b[nt]);
            // lo
            #pragma unroll
            for (int mt = 0; mt < 2; mt++) {
                uint32_t addr = st + MAT_BYTES +
                    (uint32_t)((mwarp + mt * 16 + rowA) * (PITCH * 2) + (kb + kcolA) * 2);
                ldsm_x4(a[mt][0], a[mt][1], a[mt][2], a[mt][3], addr);
            }
            #pragma unroll
            for (int mt = 0; mt < 2; mt++)
                #pragma unroll
                for (int nt = 0; nt < 8; nt++) mma16816(acc[mt][nt], a[mt], b[nt]);
        }
        if (it + 2 < NITER) load_stage((it + 2) % NSTAGE, it + 2);
        cpa_commit();
    }

    // ---------------- epilogue ----------------
    const float s_w = g_sw;
    float lmn = INFINITY, lmx = -INFINITY;

    float2 bv[8];
    #pragma unroll
    for (int nt = 0; nt < 8; nt++)
        bv[nt] = *reinterpret_cast<const float2*>(bias + colbase + nwarp + nt * 8 + (lane & 3) * 2);

    #pragma unroll
    for (int mt = 0; mt < 2; mt++) {
        #pragma unroll
        for (int half = 0; half < 2; half++) {
            const int grow = rowbase + mwarp + mt * 16 + (lane >> 2) + half * 8;
            float* dstrow = g_out + (size_t)grow * OUT + colbase + nwarp + (lane & 3) * 2;
            #pragma unroll
            for (int nt = 0; nt < 8; nt++) {
                float v0 = fmaf(s_w, acc[mt][nt][half * 2 + 0], bv[nt].x);
                float v1 = fmaf(s_w, acc[mt][nt][half * 2 + 1], bv[nt].y);
                lmn = fminf(lmn, fminf(v0, v1));
                lmx = fmaxf(lmx, fmaxf(v0, v1));
                *reinterpret_cast<float2*>(dstrow + nt * 8) = make_float2(v0, v1);
            }
        }
    }

    #pragma unroll
    for (int o = 16; o; o >>= 1) {
        lmn = fminf(lmn, __shfl_xor_sync(0xffffffffu, lmn, o));
        lmx = fmaxf(lmx, __shfl_xor_sync(0xffffffffu, lmx, o));
    }
    __shared__ float rmn[8], rmx[8];
    if (lane == 0) { rmn[wid] = lmn; rmx[wid] = lmx; }
    __syncthreads();
    if (t == 0) {
        for (int i = 1; i < 8; i++) { lmn = fminf(lmn, rmn[i]); lmx = fmaxf(lmx, rmx[i]); }
        int cl = rowbase / nPer;
        atomicMin(&g_cmin[cl], f2o(lmn));
        atomicMax(&g_cmax[cl], f2o(lmx));
    }
}

// ---------------- kernel 5: EMA range update + qparams ----------------
__global__ void range_kernel(const float* __restrict__ act_range, const int* __restrict__ cinfo,
                             float* __restrict__ out_range, int K) {
    int t = threadIdx.x;
    if (t < K) {
        out_range[2 * t]     = act_range[2 * t];
        out_range[2 * t + 1] = act_range[2 * t + 1];
    }
    __syncthreads();
    if (t < K) {
        float mn = o2f(g_cmin[t]), mx = o2f(g_cmax[t]);
        int c = cinfo[2 * t];
        float o0 = act_range[2 * c], o1 = act_range[2 * c + 1];
        float nmin = __fadd_rn(__fmul_rn(o0, 0.999f), __fmul_rn(mn, 0.001f));
        float nmax = __fadd_rn(__fmul_rn(o1, 0.999f), __fmul_rn(mx, 0.001f));
        out_range[2 * c]     = nmin;
        out_range[2 * c + 1] = nmax;
        float s = __fdiv_rn(__fsub_rn(nmax, nmin), 255.0f);
        g_s3[t] = s;
        g_z3[t] = -rintf(__fdiv_rn(nmin, s));
    }
}

// ---------------- kernel 6: fake-quantize GEMM output ----------------
__global__ void quantout_kernel(float4* __restrict__ outq, int n4, int shift) {
    const float4* src = reinterpret_cast<const float4*>(g_out);
    for (int i = blockIdx.x * blockDim.x + threadIdx.x; i < n4; i += gridDim.x * blockDim.x) {
        int k = i >> shift;
        float s = g_s3[k], z = g_z3[k];
        float4 v = src[i];
        v.x = fq(v.x, s, z); v.y = fq(v.y, s, z);
        v.z = fq(v.z, s, z); v.w = fq(v.w, s, z);
        outq[i] = v;
    }
}
// fallback when chunk4 is not a power of two
__global__ void quantout_div_kernel(float4* __restrict__ outq, int n4, int chunk4) {
    const float4* src = reinterpret_cast<const float4*>(g_out);
    for (int i = blockIdx.x * blockDim.x + threadIdx.x; i < n4; i += gridDim.x * blockDim.x) {
        int k = i / chunk4;
        float s = g_s3[k], z = g_z3[k];
        float4 v = src[i];
        v.x = fq(v.x, s, z); v.y = fq(v.y, s, z);
        v.z = fq(v.z, s, z); v.w = fq(v.w, s, z);
        outq[i] = v;
    }
}

// ---------------- launch ----------------
extern "C" void kernel_launch(void* const* d_in, const int* in_sizes, int n_in,
                              void* d_out, int out_size) {
    const float* x         = (const float*)d_in[0];
    const float* w         = (const float*)d_in[1];
    const float* bias      = (const float*)d_in[2];
    const float* act_range = (const float*)d_in[3];
    const int*   cinfo     = (const int*)d_in[4];

    const int OUT = in_sizes[2];
    const int IN  = in_sizes[1] / OUT;
    const int B   = in_sizes[0] / IN;
    const int K   = in_sizes[3] / 2;
    const int n   = B / K;

    float* outq      = (float*)d_out;
    float* out_range = outq + (size_t)B * OUT;

    const int smem_bytes = NSTAGE * STAGE_BYTES;
    cudaFuncSetAttribute(gemm_tc, cudaFuncAttributeMaxDynamicSharedMemorySize, smem_bytes);

    init_kernel<<<1, 32>>>();

    const int wn4 = (OUT * IN) / 4;
    const int wn8 = (OUT * IN) / 8;
    wminmax_kernel<<<512, 256>>>((const float4*)w, wn4);
    quantw_kernel<<<1024, 256>>>((const float4*)w, wn8);

    const int xn8 = (B * IN) / 8;
    split_kernel<<<1024, 256>>>((const float4*)x, xn8);

    dim3 grid(OUT / BN, B / BM);
    gemm_tc<<<grid, 256, smem_bytes>>>(bias, IN, OUT, n);

    range_kernel<<<1, 32>>>(act_range, cinfo, out_range, K);

    const int on4 = (B / 4) * OUT;
    const int chunk4 = (n * OUT) / 4;
    if ((chunk4 & (chunk4 - 1)) == 0) {
        int shift = 0;
        while ((1 << shift) < chunk4) shift++;
        quantout_kernel<<<2048, 256>>>((float4*)outq, on4, shift);
    } else {
        quantout_div_kernel<<<2048, 256>>>((float4*)outq, on4, chunk4);
    }
}

// round 17
// speedup vs baseline: 1.7762x; 1.6640x over previous
#include <cuda_runtime.h>
#include <cuda_fp16.h>
#include <math.h>
#include <stdint.h>

// ---------------- static scratch ----------------
static __device__ __half g_wqh[4096u * 4096u];    // W' = q - z (exact ints in fp16)
static __device__ __half g_xh[10240u * 4096u];    // fp16 x
static __device__ float g_out[10240u * 4096u];    // pre-quant GEMM output
__device__ unsigned g_wmm[2];
__device__ unsigned g_cmin[32], g_cmax[32];
__device__ float g_s3[32], g_z3[32];
__device__ float g_sw;

// ---- monotone float <-> uint encoding ----
__device__ __forceinline__ unsigned f2o(float f) {
    unsigned u = __float_as_uint(f);
    return (u & 0x80000000u) ? ~u : (u | 0x80000000u);
}
__device__ __forceinline__ float o2f(unsigned u) {
    unsigned v = (u & 0x80000000u) ? (u ^ 0x80000000u) : ~u;
    return __uint_as_float(v);
}
__device__ __forceinline__ float fq(float v, float s, float z) {
    float q = rintf(__fadd_rn(__fdiv_rn(v, s), z));
    q = fminf(fmaxf(q, 0.0f), 255.0f);
    return __fmul_rn(__fsub_rn(q, z), s);
}

// ---------------- PTX helpers ----------------
__device__ __forceinline__ uint32_t smem_u32(const void* p) {
    uint32_t a;
    asm("{ .reg .u64 t; cvta.to.shared.u64 t, %1; cvt.u32.u64 %0, t; }" : "=r"(a) : "l"(p));
    return a;
}
__device__ __forceinline__ void cpa16(uint32_t d, const void* s) {
    asm volatile("cp.async.cg.shared.global [%0], [%1], 16;" :: "r"(d), "l"(s));
}
__device__ __forceinline__ void cpa_commit() { asm volatile("cp.async.commit_group;" ::: "memory"); }
template<int N> __device__ __forceinline__ void cpa_wait() {
    asm volatile("cp.async.wait_group %0;" :: "n"(N) : "memory");
}
__device__ __forceinline__ void ldsm_x4(uint32_t& r0, uint32_t& r1, uint32_t& r2, uint32_t& r3,
                                        uint32_t addr) {
    asm volatile("ldmatrix.sync.aligned.m8n8.x4.shared.b16 {%0,%1,%2,%3}, [%4];"
                 : "=r"(r0), "=r"(r1), "=r"(r2), "=r"(r3) : "r"(addr));
}
__device__ __forceinline__ void mma16816(float* c, const uint32_t* a, const uint32_t* b) {
    asm volatile("mma.sync.aligned.m16n8k16.row.col.f32.f16.f16.f32 "
                 "{%0,%1,%2,%3}, {%4,%5,%6,%7}, {%8,%9}, {%0,%1,%2,%3};"
                 : "+f"(c[0]), "+f"(c[1]), "+f"(c[2]), "+f"(c[3])
                 : "r"(a[0]), "r"(a[1]), "r"(a[2]), "r"(a[3]), "r"(b[0]), "r"(b[1]));
}
__device__ __forceinline__ uint32_t pack_f16x2(float lo, float hi) {
    __half2 p;
    p.x = __float2half_rn(lo);
    p.y = __float2half_rn(hi);
    return *reinterpret_cast<uint32_t*>(&p);
}

// ---------------- kernel 0: reset reduction state ----------------
__global__ void init_kernel() {
    if (threadIdx.x == 0) { g_wmm[0] = 0xFFFFFFFFu; g_wmm[1] = 0u; }
    if (threadIdx.x < 32) { g_cmin[threadIdx.x] = 0xFFFFFFFFu; g_cmax[threadIdx.x] = 0u; }
}

// ---------------- kernel 1: weight min/max ----------------
__global__ void wminmax_kernel(const float4* __restrict__ w4, int n4) {
    float mn = INFINITY, mx = -INFINITY;
    for (int i = blockIdx.x * blockDim.x + threadIdx.x; i < n4; i += gridDim.x * blockDim.x) {
        float4 v = w4[i];
        mn = fminf(mn, fminf(fminf(v.x, v.y), fminf(v.z, v.w)));
        mx = fmaxf(mx, fmaxf(fmaxf(v.x, v.y), fmaxf(v.z, v.w)));
    }
    #pragma unroll
    for (int o = 16; o; o >>= 1) {
        mn = fminf(mn, __shfl_xor_sync(0xffffffffu, mn, o));
        mx = fmaxf(mx, __shfl_xor_sync(0xffffffffu, mx, o));
    }
    __shared__ float smn[8], smx[8];
    if ((threadIdx.x & 31) == 0) { smn[threadIdx.x >> 5] = mn; smx[threadIdx.x >> 5] = mx; }
    __syncthreads();
    if (threadIdx.x == 0) {
        for (int i = 1; i < (int)(blockDim.x >> 5); i++) { mn = fminf(mn, smn[i]); mx = fmaxf(mx, smx[i]); }
        atomicMin(&g_wmm[0], f2o(mn));
        atomicMax(&g_wmm[1], f2o(mx));
    }
}

// ---------------- kernel 2: W' = q - z into fp16 (exact), 16B stores ----------------
__global__ void quantw_kernel(const float4* __restrict__ w4, int n8) {
    float mn = o2f(g_wmm[0]), mx = o2f(g_wmm[1]);
    float s = __fdiv_rn(__fsub_rn(mx, mn), 255.0f);
    float z = -rintf(__fdiv_rn(mn, s));
    if (blockIdx.x == 0 && threadIdx.x == 0) g_sw = s;
    uint4* dst = reinterpret_cast<uint4*>(g_wqh);
    for (int i = blockIdx.x * blockDim.x + threadIdx.x; i < n8; i += gridDim.x * blockDim.x) {
        float4 v0 = w4[2 * i];
        float4 v1 = w4[2 * i + 1];
        float e[8] = {v0.x, v0.y, v0.z, v0.w, v1.x, v1.y, v1.z, v1.w};
        float q[8];
        #pragma unroll
        for (int j = 0; j < 8; j++)
            q[j] = fminf(fmaxf(rintf(__fadd_rn(__fdiv_rn(e[j], s), z)), 0.f), 255.f) - z;
        uint4 o;
        o.x = pack_f16x2(q[0], q[1]);
        o.y = pack_f16x2(q[2], q[3]);
        o.z = pack_f16x2(q[4], q[5]);
        o.w = pack_f16x2(q[6], q[7]);
        dst[i] = o;
    }
}

// ---------------- kernel 3: x -> fp16, 16B stores ----------------
__global__ void split_kernel(const float4* __restrict__ x4, int n8) {
    uint4* xh4 = reinterpret_cast<uint4*>(g_xh);
    for (int i = blockIdx.x * blockDim.x + threadIdx.x; i < n8; i += gridDim.x * blockDim.x) {
        float4 v0 = x4[2 * i];
        float4 v1 = x4[2 * i + 1];
        uint4 o;
        o.x = pack_f16x2(v0.x, v0.y);
        o.y = pack_f16x2(v0.z, v0.w);
        o.z = pack_f16x2(v1.x, v1.y);
        o.w = pack_f16x2(v1.z, v1.w);
        xh4[i] = o;
    }
}

// ---------------- kernel 4: HMMA GEMM  out = s_w*(x_fp16 @ W'^T) + bias ----------------
// CTA tile 128x128, BK=32, 8 warps (4m x 2n), warp tile 32x64, 3-stage cp.async,
// 2 CTAs/SM, prefetch AFTER compute (round-12 shell; single fp16 pass).
#define BM 128
#define BN 128
#define BK 32
#define PITCH 40                      // fp16 elements per smem row (80 B, conflict-free)
#define MAT_BYTES (128 * PITCH * 2)   // 10240 B per matrix
#define STAGE_BYTES (2 * MAT_BYTES)   // A, B = 20480 B
#define NSTAGE 3

__global__ __launch_bounds__(256, 2)
void gemm_tc(const float* __restrict__ bias, int IN, int OUT, int nPer) {
    extern __shared__ char dsm[];
    const uint32_t sb = smem_u32(dsm);
    const int t = threadIdx.x;
    const int wid = t >> 5;
    const int lane = t & 31;
    const int wm = wid & 3;            // 4 m-warps
    const int wn = wid >> 2;           // 2 n-warps
    const int mwarp = wm * 32;
    const int nwarp = wn * 64;
    const int rowbase = blockIdx.y * BM;
    const int colbase = blockIdx.x * BN;
    const int NITER = IN / BK;

    const __half* xh = g_xh;
    const __half* wqh = g_wqh;

    // stage loader: 1024 x 16B chunks (A 512, B 512), 4 per thread
    auto load_stage = [&](int s, int it) {
        const int k0 = it * BK;
        const uint32_t st = sb + s * STAGE_BYTES;
        #pragma unroll
        for (int j = 0; j < 4; j++) {
            const int m = j >> 1;                 // 0: x, 1: W'
            const int ci = ((j & 1) << 8) + t;    // 0..511
            const int r = ci >> 2, c = ci & 3;
            uint32_t dst = st + (uint32_t)(m * MAT_BYTES + r * (PITCH * 2) + c * 16);
            const __half* src;
            if (m == 0) src = xh  + (size_t)(rowbase + r) * IN + k0 + c * 8;
            else        src = wqh + (size_t)(colbase + r) * IN + k0 + c * 8;
            cpa16(dst, src);
        }
    };

    // ldmatrix per-thread address components
    const int rowA = lane & 15;                           // row within 16-row tile
    const int kcolA = (lane >> 4) << 3;                   // 0 or 8
    const int rowB = (lane & 7) + ((lane >> 4) & 1) * 8;  // row within 16-row pair of n-tiles
    const int kcolB = ((lane >> 3) & 1) << 3;             // 0 or 8

    float acc[2][8][4];
    #pragma unroll
    for (int i = 0; i < 2; i++)
        #pragma unroll
        for (int j = 0; j < 8; j++)
            #pragma unroll
            for (int e = 0; e < 4; e++) acc[i][j][e] = 0.0f;

    load_stage(0, 0); cpa_commit();
    load_stage(1, 1); cpa_commit();

    for (int it = 0; it < NITER; ++it) {
        const int s = it % NSTAGE;
        cpa_wait<1>();
        __syncthreads();
        const uint32_t st = sb + s * STAGE_BYTES;
        #pragma unroll
        for (int kk = 0; kk < 2; kk++) {
            const int kb = kk * 16;
            // B: 8 n-tiles via 4 paired ldmatrix.x4 (2 n-tiles each)
            uint32_t b[8][2];
            #pragma unroll
            for (int np = 0; np < 4; np++) {
                uint32_t addr = st + MAT_BYTES +
                    (uint32_t)((nwarp + np * 16 + rowB) * (PITCH * 2) + (kb + kcolB) * 2);
                ldsm_x4(b[2 * np][0], b[2 * np][1], b[2 * np + 1][0], b[2 * np + 1][1], addr);
            }
            uint32_t a[2][4];
            #pragma unroll
            for (int mt = 0; mt < 2; mt++) {
                uint32_t addr = st +
                    (uint32_t)((mwarp + mt * 16 + rowA) * (PITCH * 2) + (kb + kcolA) * 2);
                ldsm_x4(a[mt][0], a[mt][1], a[mt][2], a[mt][3], addr);
            }
            #pragma unroll
            for (int mt = 0; mt < 2; mt++)
                #pragma unroll
                for (int nt = 0; nt < 8; nt++) mma16816(acc[mt][nt], a[mt], b[nt]);
        }
        if (it + 2 < NITER) load_stage((it + 2) % NSTAGE, it + 2);
        cpa_commit();
    }

    // ---------------- epilogue ----------------
    const float s_w = g_sw;
    float lmn = INFINITY, lmx = -INFINITY;

    float2 bv[8];
    #pragma unroll
    for (int nt = 0; nt < 8; nt++)
        bv[nt] = *reinterpret_cast<const float2*>(bias + colbase + nwarp + nt * 8 + (lane & 3) * 2);

    #pragma unroll
    for (int mt = 0; mt < 2; mt++) {
        #pragma unroll
        for (int half = 0; half < 2; half++) {
            const int grow = rowbase + mwarp + mt * 16 + (lane >> 2) + half * 8;
            float* dstrow = g_out + (size_t)grow * OUT + colbase + nwarp + (lane & 3) * 2;
            #pragma unroll
            for (int nt = 0; nt < 8; nt++) {
                float v0 = fmaf(s_w, acc[mt][nt][half * 2 + 0], bv[nt].x);
                float v1 = fmaf(s_w, acc[mt][nt][half * 2 + 1], bv[nt].y);
                lmn = fminf(lmn, fminf(v0, v1));
                lmx = fmaxf(lmx, fmaxf(v0, v1));
                *reinterpret_cast<float2*>(dstrow + nt * 8) = make_float2(v0, v1);
            }
        }
    }

    #pragma unroll
    for (int o = 16; o; o >>= 1) {
        lmn = fminf(lmn, __shfl_xor_sync(0xffffffffu, lmn, o));
        lmx = fmaxf(lmx, __shfl_xor_sync(0xffffffffu, lmx, o));
    }
    __shared__ float rmn[8], rmx[8];
    if (lane == 0) { rmn[wid] = lmn; rmx[wid] = lmx; }
    __syncthreads();
    if (t == 0) {
        for (int i = 1; i < 8; i++) { lmn = fminf(lmn, rmn[i]); lmx = fmaxf(lmx, rmx[i]); }
        int cl = rowbase / nPer;
        atomicMin(&g_cmin[cl], f2o(lmn));
        atomicMax(&g_cmax[cl], f2o(lmx));
    }
}

// ---------------- kernel 5: EMA range update + qparams ----------------
__global__ void range_kernel(const float* __restrict__ act_range, const int* __restrict__ cinfo,
                             float* __restrict__ out_range, int K) {
    int t = threadIdx.x;
    if (t < K) {
        out_range[2 * t]     = act_range[2 * t];
        out_range[2 * t + 1] = act_range[2 * t + 1];
    }
    __syncthreads();
    if (t < K) {
        float mn = o2f(g_cmin[t]), mx = o2f(g_cmax[t]);
        int c = cinfo[2 * t];
        float o0 = act_range[2 * c], o1 = act_range[2 * c + 1];
        float nmin = __fadd_rn(__fmul_rn(o0, 0.999f), __fmul_rn(mn, 0.001f));
        float nmax = __fadd_rn(__fmul_rn(o1, 0.999f), __fmul_rn(mx, 0.001f));
        out_range[2 * c]     = nmin;
        out_range[2 * c + 1] = nmax;
        float s = __fdiv_rn(__fsub_rn(nmax, nmin), 255.0f);
        g_s3[t] = s;
        g_z3[t] = -rintf(__fdiv_rn(nmin, s));
    }
}

// ---------------- kernel 6: fake-quantize GEMM output ----------------
__global__ void quantout_kernel(float4* __restrict__ outq, int n4, int shift) {
    const float4* src = reinterpret_cast<const float4*>(g_out);
    for (int i = blockIdx.x * blockDim.x + threadIdx.x; i < n4; i += gridDim.x * blockDim.x) {
        int k = i >> shift;
        float s = g_s3[k], z = g_z3[k];
        float4 v = src[i];
        v.x = fq(v.x, s, z); v.y = fq(v.y, s, z);
        v.z = fq(v.z, s, z); v.w = fq(v.w, s, z);
        outq[i] = v;
    }
}
// fallback when chunk4 is not a power of two
__global__ void quantout_div_kernel(float4* __restrict__ outq, int n4, int chunk4) {
    const float4* src = reinterpret_cast<const float4*>(g_out);
    for (int i = blockIdx.x * blockDim.x + threadIdx.x; i < n4; i += gridDim.x * blockDim.x) {
        int k = i / chunk4;
        float s = g_s3[k], z = g_z3[k];
        float4 v = src[i];
        v.x = fq(v.x, s, z); v.y = fq(v.y, s, z);
        v.z = fq(v.z, s, z); v.w = fq(v.w, s, z);
        outq[i] = v;
    }
}

// ---------------- launch ----------------
extern "C" void kernel_launch(void* const* d_in, const int* in_sizes, int n_in,
                              void* d_out, int out_size) {
    const float* x         = (const float*)d_in[0];
    const float* w         = (const float*)d_in[1];
    const float* bias      = (const float*)d_in[2];
    const float* act_range = (const float*)d_in[3];
    const int*   cinfo     = (const int*)d_in[4];

    const int OUT = in_sizes[2];
    const int IN  = in_sizes[1] / OUT;
    const int B   = in_sizes[0] / IN;
    const int K   = in_sizes[3] / 2;
    const int n   = B / K;

    float* outq      = (float*)d_out;
    float* out_range = outq + (size_t)B * OUT;

    const int smem_bytes = NSTAGE * STAGE_BYTES;   // 61440
    cudaFuncSetAttribute(gemm_tc, cudaFuncAttributeMaxDynamicSharedMemorySize, smem_bytes);

    init_kernel<<<1, 32>>>();

    const int wn4 = (OUT * IN) / 4;
    const int wn8 = (OUT * IN) / 8;
    wminmax_kernel<<<512, 256>>>((const float4*)w, wn4);
    quantw_kernel<<<1024, 256>>>((const float4*)w, wn8);

    const int xn8 = (B * IN) / 8;
    split_kernel<<<1024, 256>>>((const float4*)x, xn8);

    dim3 grid(OUT / BN, B / BM);
    gemm_tc<<<grid, 256, smem_bytes>>>(bias, IN, OUT, n);

    range_kernel<<<1, 32>>>(act_range, cinfo, out_range, K);

    const int on4 = (B / 4) * OUT;
    const int chunk4 = (n * OUT) / 4;
    if ((chunk4 & (chunk4 - 1)) == 0) {
        int shift = 0;
        while ((1 << shift) < chunk4) shift++;
        quantout_kernel<<<2048, 256>>>((float4*)outq, on4, shift);
    } else {
        quantout_div_kernel<<<2048, 256>>>((float4*)outq, on4, chunk4);
    }
}